// round 14
// baseline (speedup 1.0000x reference)
#include <cuda_runtime.h>
#include <cstdint>

// LTC scan, round 14 — FUSED: xin computed inside the scan kernel.
// R13 post-mortem: xin stuck at ~280us (latency-bound like the scan, no cheap
// standalone fix) while the scan idles 60% of issue slots.
// R14: delete xin_kernel. Each scan CTA computes xin(t+1) for its own 2 rows
// during timestep t's u=0 tick: W_in rows via LDG (L1-resident, shared by both
// CTAs/SM), x staged through a double-buffered smem slab fenced by the existing
// unfold barriers. b_in+b_r folded into one constant. No new barriers.

#define Bsz 512
#define Ssz 512
#define Dsz 128
#define Hsz 128
#define UNFOLDS 6
#define HSTRIDE 136   // 128 + 4 (pad at k=64) + 4 (row-stride bank shift)

typedef unsigned long long ull;

__device__ __forceinline__ ull ffma2(ull a, ull b, ull c) {
    ull d;
    asm("fma.rn.f32x2 %0, %1, %2, %3;" : "=l"(d) : "l"(a), "l"(b), "l"(c));
    return d;
}

__device__ __forceinline__ float f2sum(ull v) {
    float lo, hi;
    asm("mov.b64 {%0, %1}, %2;" : "=f"(lo), "=f"(hi) : "l"(v));
    return lo + hi;
}

__device__ __forceinline__ float ftanh(float s) {
    float y;
    asm("tanh.approx.f32 %0, %1;" : "=f"(y) : "f"(s));   // MUFU.TANH
    return y;
}

// ---------------------------------------------------------------------------
// Fused kernel: grid 256 x 128 threads, 2 batch rows/CTA, 2 CTAs/SM.
// Thread (p = tid>>1, hf = tid&1): units j0=2p, 2p+1 over k-half [64hf,64hf+64);
// owns states (j0, row hf), (j0+1, row hf). 1 __syncthreads/unfold.
// xin(t+1) dot runs in the u=0 tick (independent work -> fills issue bubbles).
// ---------------------------------------------------------------------------
__global__ void __launch_bounds__(128, 2)
ltc_fused(const float* __restrict__ x,
          const float* __restrict__ W_in,
          const float* __restrict__ b_in,
          const float* __restrict__ W_r,
          const float* __restrict__ b_r,
          const float* __restrict__ W_fc,
          const float* __restrict__ b_fc,
          float* __restrict__ out)
{
    __shared__ float hs[2][2][HSTRIDE];   // [buf][row][padded k] hidden state
    __shared__ float xs2[2][2][Dsz];      // [buf][row][d] staged x
    __shared__ float red[2][64];

    const int tid  = threadIdx.x;
    const int p    = tid >> 1;
    const int hf   = tid & 1;
    const int j0   = 2 * p;
    const int base = blockIdx.x * 2;
    const int koff = hf * 68;                   // 64 floats + 4-float pad at k=64
    const int jph  = j0 + (j0 >= 64 ? 4 : 0);   // padded publish index
    const int rowM = hf * HSTRIDE;
    const int rowO = (hf ^ 1) * HSTRIDE;
    const int offM = rowM + koff;
    const int offO = rowO + koff;
    const int offP = rowM + jph;

    // W_r rows j0, j0+1, cols [64hf, 64hf+64): 128 floats in registers.
    ull wA[32], wB[32];
    {
        const ulonglong2* wpA = (const ulonglong2*)(W_r + (size_t)j0 * Hsz + 64 * hf);
        const ulonglong2* wpB = (const ulonglong2*)(W_r + (size_t)(j0 + 1) * Hsz + 64 * hf);
        #pragma unroll
        for (int c = 0; c < 16; ++c) {
            ulonglong2 vA = wpA[c];
            ulonglong2 vB = wpB[c];
            wA[2 * c] = vA.x;  wA[2 * c + 1] = vA.y;
            wB[2 * c] = vB.x;  wB[2 * c + 1] = vB.y;
        }
    }

    // Folded constant per unit: b_in[j] + b_r[j].
    const float cA = b_in[j0]     + b_r[j0];
    const float cB = b_in[j0 + 1] + b_r[j0 + 1];

    // W_in rows for the in-loop xin dot (LDG, L1-resident).
    const ulonglong2* wiA = (const ulonglong2*)(W_in + (size_t)j0 * Dsz + 64 * hf);
    const ulonglong2* wiB = (const ulonglong2*)(W_in + (size_t)(j0 + 1) * Dsz + 64 * hf);

    const float* xg0 = x + (size_t)(base + 0) * Ssz * Dsz;
    const float* xg1 = x + (size_t)(base + 1) * Ssz * Dsz;

    float h0 = 0.f, h1 = 0.f;

    // Bootstrap: publish h=0, stage x(0).
    hs[0][0][offP]     = 0.f;
    hs[0][0][offP + 1] = 0.f;
    xs2[0][0][tid] = xg0[tid];
    xs2[0][1][tid] = xg1[tid];
    __syncthreads();

    // xin(0): dot over my k-half for both rows, shfl-combine, keep my row.
    float xinA, xinB;
    {
        ull A0 = 0ull, B0 = 0ull, A1 = 0ull, B1 = 0ull;
        const float* x0 = &xs2[0][0][64 * hf];
        const float* x1 = &xs2[0][1][64 * hf];
        #pragma unroll
        for (int c = 0; c < 16; ++c) {
            ulonglong2 wa = wiA[c], wb = wiB[c];
            ulonglong2 v0 = *(const ulonglong2*)(x0 + 4 * c);
            ulonglong2 v1 = *(const ulonglong2*)(x1 + 4 * c);
            A0 = ffma2(wa.x, v0.x, A0);  A0 = ffma2(wa.y, v0.y, A0);
            B0 = ffma2(wb.x, v0.x, B0);  B0 = ffma2(wb.y, v0.y, B0);
            A1 = ffma2(wa.x, v1.x, A1);  A1 = ffma2(wa.y, v1.y, A1);
            B1 = ffma2(wb.x, v1.x, B1);  B1 = ffma2(wb.y, v1.y, B1);
        }
        const float pA0 = f2sum(A0), pB0 = f2sum(B0);
        const float pA1 = f2sum(A1), pB1 = f2sum(B1);
        const float keepA = hf ? pA1 : pA0, sendA = hf ? pA0 : pA1;
        const float keepB = hf ? pB1 : pB0, sendB = hf ? pB0 : pB1;
        xinA = keepA + __shfl_xor_sync(0xffffffffu, sendA, 1) + cA;
        xinB = keepB + __shfl_xor_sync(0xffffffffu, sendB, 1) + cB;
    }

    // Prefetch x(1) into registers.
    float xr0 = xg0[Dsz + tid];
    float xr1 = xg1[Dsz + tid];

    #pragma unroll 1
    for (int t = 0; t < Ssz; ++t) {
        // Stage x(t+1); prefetch x(t+2). Fenced by the u=0 barrier below.
        const int nb = (t + 1) & 1;
        xs2[nb][0][tid] = xr0;
        xs2[nb][1][tid] = xr1;
        const int tn = (t + 2 < Ssz) ? (t + 2) : (Ssz - 1);
        xr0 = xg0[(size_t)tn * Dsz + tid];
        xr1 = xg1[(size_t)tn * Dsz + tid];

        float nxA = 0.f, nxB = 0.f;   // xin(t+1), produced in the u=0 tick

        #pragma unroll 1
        for (int u = 0; u < UNFOLDS; ++u) {
            const float* hb = hs[u & 1][0];
            float*       hn = hs[(u + 1) & 1][0];
            __syncthreads();

            // h dot: units j0, j0+1 x {my row, other row} over my k-half.
            ull a0 = 0ull, a1 = 0ull, b0 = 0ull, b1 = 0ull;   // my row
            ull c0 = 0ull, c1 = 0ull, d0 = 0ull, d1 = 0ull;   // other row
            #pragma unroll
            for (int c = 0; c < 16; ++c) {
                ulonglong2 vM = *(const ulonglong2*)(hb + offM + 4 * c);
                ulonglong2 vO = *(const ulonglong2*)(hb + offO + 4 * c);
                a0 = ffma2(wA[2 * c],     vM.x, a0);
                b0 = ffma2(wB[2 * c],     vM.x, b0);
                a1 = ffma2(wA[2 * c + 1], vM.y, a1);
                b1 = ffma2(wB[2 * c + 1], vM.y, b1);
                c0 = ffma2(wA[2 * c],     vO.x, c0);
                d0 = ffma2(wB[2 * c],     vO.x, d0);
                c1 = ffma2(wA[2 * c + 1], vO.y, c1);
                d1 = ffma2(wB[2 * c + 1], vO.y, d1);
            }

            // Independent xin(t+1) dot fills this tick's latency bubbles.
            if (u == 0) {
                ull A0 = 0ull, B0 = 0ull, A1 = 0ull, B1 = 0ull;
                const float* x0 = &xs2[nb][0][64 * hf];
                const float* x1 = &xs2[nb][1][64 * hf];
                #pragma unroll
                for (int c = 0; c < 16; ++c) {
                    ulonglong2 wa = wiA[c], wb = wiB[c];
                    ulonglong2 v0 = *(const ulonglong2*)(x0 + 4 * c);
                    ulonglong2 v1 = *(const ulonglong2*)(x1 + 4 * c);
                    A0 = ffma2(wa.x, v0.x, A0);  A0 = ffma2(wa.y, v0.y, A0);
                    B0 = ffma2(wb.x, v0.x, B0);  B0 = ffma2(wb.y, v0.y, B0);
                    A1 = ffma2(wa.x, v1.x, A1);  A1 = ffma2(wa.y, v1.y, A1);
                    B1 = ffma2(wb.x, v1.x, B1);  B1 = ffma2(wb.y, v1.y, B1);
                }
                const float pA0 = f2sum(A0), pB0 = f2sum(B0);
                const float pA1 = f2sum(A1), pB1 = f2sum(B1);
                const float keepA = hf ? pA1 : pA0, sendA = hf ? pA0 : pA1;
                const float keepB = hf ? pB1 : pB0, sendB = hf ? pB0 : pB1;
                nxA = keepA + __shfl_xor_sync(0xffffffffu, sendA, 1) + cA;
                nxB = keepB + __shfl_xor_sync(0xffffffffu, sendB, 1) + cB;
            }

            const float PaM = f2sum(a0) + f2sum(a1);
            const float PbM = f2sum(b0) + f2sum(b1);
            const float PaO = f2sum(c0) + f2sum(c1);
            const float PbO = f2sum(d0) + f2sum(d1);

            const float recvA = __shfl_xor_sync(0xffffffffu, PaO, 1);
            const float recvB = __shfl_xor_sync(0xffffffffu, PbO, 1);

            h0 = 0.9f * h0 + 0.1f * ftanh(PaM + recvA + xinA);
            h1 = 0.9f * h1 + 0.1f * ftanh(PbM + recvB + xinB);

            float2 st;  st.x = h0;  st.y = h1;
            *(float2*)(hn + offP) = st;
        }

        xinA = nxA;
        xinB = nxB;
    }

    // out[b] = b_fc + sum_j h[b][j] * W_fc[j]
    __syncthreads();
    {
        const float2 wfc2 = *(const float2*)&W_fc[j0];
        red[hf][p] = h0 * wfc2.x + h1 * wfc2.y;
    }
    __syncthreads();

    const int wid = tid >> 5, lane = tid & 31;
    if (wid < 2) {
        float s = red[wid][lane] + red[wid][lane + 32];
        #pragma unroll
        for (int d = 16; d > 0; d >>= 1)
            s += __shfl_xor_sync(0xffffffffu, s, d);
        if (lane == 0)
            out[base + wid] = s + b_fc[0];
    }
}

extern "C" void kernel_launch(void* const* d_in, const int* in_sizes, int n_in,
                              void* d_out, int out_size)
{
    const float* x    = (const float*)d_in[0];
    const float* W_in = (const float*)d_in[1];
    const float* b_in = (const float*)d_in[2];
    const float* W_r  = (const float*)d_in[3];
    const float* b_r  = (const float*)d_in[4];
    const float* W_fc = (const float*)d_in[5];
    const float* b_fc = (const float*)d_in[6];
    float* out = (float*)d_out;

    ltc_fused<<<Bsz / 2, 128>>>(x, W_in, b_in, W_r, b_r, W_fc, b_fc, out);
}

// round 15
// speedup vs baseline: 1.0243x; 1.0243x over previous
#include <cuda_runtime.h>
#include <cstdint>

// LTC scan, round 15 — fusion retry with separated live ranges.
// R14 post-mortem: xin dot nested inside the u==0 tick made xin accumulators
// + W_in loads live ALONGSIDE the h-dot accumulators + wA/wB[128] -> 255 regs,
// spills (L2 26%), 2.7x regression. Concept not disproven; placement was.
// R15: xin(t+1) computed as its OWN phase after the unfold loop (h-dot
// accumulators dead there); xin loop unrolled only 4x to bound transient
// pressure. W_in via LDG (L1-resident, both CTAs share). Gate: regs <= ~235.

#define Bsz 512
#define Ssz 512
#define Dsz 128
#define Hsz 128
#define UNFOLDS 6
#define HSTRIDE 136   // 128 + 4 (pad at k=64) + 4 (row-stride bank shift)

typedef unsigned long long ull;

__device__ __forceinline__ ull ffma2(ull a, ull b, ull c) {
    ull d;
    asm("fma.rn.f32x2 %0, %1, %2, %3;" : "=l"(d) : "l"(a), "l"(b), "l"(c));
    return d;
}

__device__ __forceinline__ float f2sum(ull v) {
    float lo, hi;
    asm("mov.b64 {%0, %1}, %2;" : "=f"(lo), "=f"(hi) : "l"(v));
    return lo + hi;
}

__device__ __forceinline__ float ftanh(float s) {
    float y;
    asm("tanh.approx.f32 %0, %1;" : "=f"(y) : "f"(s));   // MUFU.TANH
    return y;
}

// ---------------------------------------------------------------------------
// Fused kernel: grid 256 x 128 threads, 2 batch rows/CTA, 2 CTAs/SM.
// Thread (p = tid>>1, hf = tid&1): units j0=2p, 2p+1 over k-half [64hf,64hf+64);
// owns states (j0, row hf), (j0+1, row hf). 1 __syncthreads/unfold.
// xin(t+1) phase AFTER the unfolds (h-dot registers dead there).
// ---------------------------------------------------------------------------
__global__ void __launch_bounds__(128, 2)
ltc_fused(const float* __restrict__ x,
          const float* __restrict__ W_in,
          const float* __restrict__ b_in,
          const float* __restrict__ W_r,
          const float* __restrict__ b_r,
          const float* __restrict__ W_fc,
          const float* __restrict__ b_fc,
          float* __restrict__ out)
{
    __shared__ float hs[2][2][HSTRIDE];   // [buf][row][padded k] hidden state
    __shared__ float xs2[2][2][Dsz];      // [buf][row][d] staged x
    __shared__ float red[2][64];

    const int tid  = threadIdx.x;
    const int p    = tid >> 1;
    const int hf   = tid & 1;
    const int j0   = 2 * p;
    const int base = blockIdx.x * 2;
    const int koff = hf * 68;                   // 64 floats + 4-float pad at k=64
    const int jph  = j0 + (j0 >= 64 ? 4 : 0);   // padded publish index
    const int rowM = hf * HSTRIDE;
    const int rowO = (hf ^ 1) * HSTRIDE;
    const int offM = rowM + koff;
    const int offO = rowO + koff;
    const int offP = rowM + jph;

    // W_r rows j0, j0+1, cols [64hf, 64hf+64): 128 floats in registers.
    ull wA[32], wB[32];
    {
        const ulonglong2* wpA = (const ulonglong2*)(W_r + (size_t)j0 * Hsz + 64 * hf);
        const ulonglong2* wpB = (const ulonglong2*)(W_r + (size_t)(j0 + 1) * Hsz + 64 * hf);
        #pragma unroll
        for (int c = 0; c < 16; ++c) {
            ulonglong2 vA = wpA[c];
            ulonglong2 vB = wpB[c];
            wA[2 * c] = vA.x;  wA[2 * c + 1] = vA.y;
            wB[2 * c] = vB.x;  wB[2 * c + 1] = vB.y;
        }
    }

    // Folded constant per unit: b_in[j] + b_r[j].
    const float cA = b_in[j0]     + b_r[j0];
    const float cB = b_in[j0 + 1] + b_r[j0 + 1];

    // W_in row pointers for the per-timestep xin phase (LDG, L1-resident).
    const ulonglong2* wiA = (const ulonglong2*)(W_in + (size_t)j0 * Dsz + 64 * hf);
    const ulonglong2* wiB = (const ulonglong2*)(W_in + (size_t)(j0 + 1) * Dsz + 64 * hf);

    const float* xg0 = x + (size_t)(base + 0) * Ssz * Dsz;
    const float* xg1 = x + (size_t)(base + 1) * Ssz * Dsz;

    float h0 = 0.f, h1 = 0.f;

    // Bootstrap: publish h=0, stage x(0), compute xin(0).
    hs[0][0][offP]     = 0.f;
    hs[0][0][offP + 1] = 0.f;
    xs2[0][0][tid] = xg0[tid];
    xs2[0][1][tid] = xg1[tid];
    __syncthreads();

    float xinA, xinB;
    {
        ull A0 = 0ull, B0 = 0ull, A1 = 0ull, B1 = 0ull;
        const float* x0 = &xs2[0][0][64 * hf];
        const float* x1 = &xs2[0][1][64 * hf];
        #pragma unroll 4
        for (int c = 0; c < 16; ++c) {
            ulonglong2 wa = wiA[c], wb = wiB[c];
            ulonglong2 v0 = *(const ulonglong2*)(x0 + 4 * c);
            ulonglong2 v1 = *(const ulonglong2*)(x1 + 4 * c);
            A0 = ffma2(wa.x, v0.x, A0);  A0 = ffma2(wa.y, v0.y, A0);
            B0 = ffma2(wb.x, v0.x, B0);  B0 = ffma2(wb.y, v0.y, B0);
            A1 = ffma2(wa.x, v1.x, A1);  A1 = ffma2(wa.y, v1.y, A1);
            B1 = ffma2(wb.x, v1.x, B1);  B1 = ffma2(wb.y, v1.y, B1);
        }
        const float pA0 = f2sum(A0), pB0 = f2sum(B0);
        const float pA1 = f2sum(A1), pB1 = f2sum(B1);
        const float keepA = hf ? pA1 : pA0, sendA = hf ? pA0 : pA1;
        const float keepB = hf ? pB1 : pB0, sendB = hf ? pB0 : pB1;
        xinA = keepA + __shfl_xor_sync(0xffffffffu, sendA, 1) + cA;
        xinB = keepB + __shfl_xor_sync(0xffffffffu, sendB, 1) + cB;
    }

    #pragma unroll 1
    for (int t = 0; t < Ssz; ++t) {
        // Stage x(t+1) into buffer (t+1)&1 (read at the bottom of this
        // timestep, 6 barriers later; buffer parity keeps writes/reads apart).
        const int nb = (t + 1) & 1;
        {
            const int tn = (t + 1 < Ssz) ? (t + 1) : t;
            xs2[nb][0][tid] = xg0[(size_t)tn * Dsz + tid];
            xs2[nb][1][tid] = xg1[(size_t)tn * Dsz + tid];
        }

        #pragma unroll 1
        for (int u = 0; u < UNFOLDS; ++u) {
            const float* hb = hs[u & 1][0];
            float*       hn = hs[(u + 1) & 1][0];
            __syncthreads();

            ull a0 = 0ull, a1 = 0ull, b0 = 0ull, b1 = 0ull;   // my row
            ull c0 = 0ull, c1 = 0ull, d0 = 0ull, d1 = 0ull;   // other row
            #pragma unroll
            for (int c = 0; c < 16; ++c) {
                ulonglong2 vM = *(const ulonglong2*)(hb + offM + 4 * c);
                ulonglong2 vO = *(const ulonglong2*)(hb + offO + 4 * c);
                a0 = ffma2(wA[2 * c],     vM.x, a0);
                b0 = ffma2(wB[2 * c],     vM.x, b0);
                a1 = ffma2(wA[2 * c + 1], vM.y, a1);
                b1 = ffma2(wB[2 * c + 1], vM.y, b1);
                c0 = ffma2(wA[2 * c],     vO.x, c0);
                d0 = ffma2(wB[2 * c],     vO.x, d0);
                c1 = ffma2(wA[2 * c + 1], vO.y, c1);
                d1 = ffma2(wB[2 * c + 1], vO.y, d1);
            }
            const float PaM = f2sum(a0) + f2sum(a1);
            const float PbM = f2sum(b0) + f2sum(b1);
            const float PaO = f2sum(c0) + f2sum(c1);
            const float PbO = f2sum(d0) + f2sum(d1);

            const float recvA = __shfl_xor_sync(0xffffffffu, PaO, 1);
            const float recvB = __shfl_xor_sync(0xffffffffu, PbO, 1);

            h0 = 0.9f * h0 + 0.1f * ftanh(PaM + recvA + xinA);
            h1 = 0.9f * h1 + 0.1f * ftanh(PbM + recvB + xinB);

            float2 st;  st.x = h0;  st.y = h1;
            *(float2*)(hn + offP) = st;
        }

        // xin(t+1) phase: h-dot accumulators are dead here -> low pressure.
        {
            ull A0 = 0ull, B0 = 0ull, A1 = 0ull, B1 = 0ull;
            const float* x0 = &xs2[nb][0][64 * hf];
            const float* x1 = &xs2[nb][1][64 * hf];
            #pragma unroll 4
            for (int c = 0; c < 16; ++c) {
                ulonglong2 wa = wiA[c], wb = wiB[c];
                ulonglong2 v0 = *(const ulonglong2*)(x0 + 4 * c);
                ulonglong2 v1 = *(const ulonglong2*)(x1 + 4 * c);
                A0 = ffma2(wa.x, v0.x, A0);  A0 = ffma2(wa.y, v0.y, A0);
                B0 = ffma2(wb.x, v0.x, B0);  B0 = ffma2(wb.y, v0.y, B0);
                A1 = ffma2(wa.x, v1.x, A1);  A1 = ffma2(wa.y, v1.y, A1);
                B1 = ffma2(wb.x, v1.x, B1);  B1 = ffma2(wb.y, v1.y, B1);
            }
            const float pA0 = f2sum(A0), pB0 = f2sum(B0);
            const float pA1 = f2sum(A1), pB1 = f2sum(B1);
            const float keepA = hf ? pA1 : pA0, sendA = hf ? pA0 : pA1;
            const float keepB = hf ? pB1 : pB0, sendB = hf ? pB0 : pB1;
            xinA = keepA + __shfl_xor_sync(0xffffffffu, sendA, 1) + cA;
            xinB = keepB + __shfl_xor_sync(0xffffffffu, sendB, 1) + cB;
        }
    }

    // out[b] = b_fc + sum_j h[b][j] * W_fc[j]
    __syncthreads();
    {
        const float2 wfc2 = *(const float2*)&W_fc[j0];
        red[hf][p] = h0 * wfc2.x + h1 * wfc2.y;
    }
    __syncthreads();

    const int wid = tid >> 5, lane = tid & 31;
    if (wid < 2) {
        float s = red[wid][lane] + red[wid][lane + 32];
        #pragma unroll
        for (int d = 16; d > 0; d >>= 1)
            s += __shfl_xor_sync(0xffffffffu, s, d);
        if (lane == 0)
            out[base + wid] = s + b_fc[0];
    }
}

extern "C" void kernel_launch(void* const* d_in, const int* in_sizes, int n_in,
                              void* d_out, int out_size)
{
    const float* x    = (const float*)d_in[0];
    const float* W_in = (const float*)d_in[1];
    const float* b_in = (const float*)d_in[2];
    const float* W_r  = (const float*)d_in[3];
    const float* b_r  = (const float*)d_in[4];
    const float* W_fc = (const float*)d_in[5];
    const float* b_fc = (const float*)d_in[6];
    float* out = (float*)d_out;

    ltc_fused<<<Bsz / 2, 128>>>(x, W_in, b_in, W_r, b_r, W_fc, b_fc, out);
}

// round 16
// speedup vs baseline: 1.7170x; 1.6762x over previous
#include <cuda_runtime.h>
#include <cstdint>

// LTC scan, round 16.
// R15 post-mortem: fused W_in-via-LDG re-streams 64KB through L1 512x
// (32 lines/instr) -> fusion dead. Revert to two kernels (R13 = 1678us).
// Floor model: scan ~1240us (FFMA2 rt3), xin ~180us. Scan kept verbatim.
// R16 work item: xin occupancy 2->4 warps/SMSP under the (256,2) 128-reg cap:
// thread = (unit-pair, k-QUARTER), W regs 64, 4 rows/chunk (peak ~110 regs),
// 2-round butterfly combine (xor2, xor1); lane q finalizes row q.

#define Bsz 512
#define Ssz 512
#define Dsz 128
#define Hsz 128
#define UNFOLDS 6
#define HSTRIDE 136   // scan: 128 + 4 (pad at k=64) + 4 (row-stride bank shift)
#define XROW 132      // xin: padded row stride

typedef unsigned long long ull;

__device__ float g_xin[(size_t)Bsz * Ssz * Hsz];   // [b][s][h] scratch

__device__ __forceinline__ ull ffma2(ull a, ull b, ull c) {
    ull d;
    asm("fma.rn.f32x2 %0, %1, %2, %3;" : "=l"(d) : "l"(a), "l"(b), "l"(c));
    return d;
}

__device__ __forceinline__ float f2sum(ull v) {
    float lo, hi;
    asm("mov.b64 {%0, %1}, %2;" : "=f"(lo), "=f"(hi) : "l"(v));
    return lo + hi;
}

__device__ __forceinline__ float ftanh(float s) {
    float y;
    asm("tanh.approx.f32 %0, %1;" : "=f"(y) : "f"(s));   // MUFU.TANH
    return y;
}

// ---------------------------------------------------------------------------
// Kernel 1: xin[b,s,j] = sum_d x[b,s,d] * W_in[j,d] + b_in[j]
// 256 threads, 2 CTAs/SM (4 warps/SMSP). Thread (p = tid>>2, q = tid&3):
// units j0=2p, 2p+1 over k-quarter [32q, 32q+32). 4 rows/chunk, 32 chunks.
// Butterfly combine: xor2 (quarter pairs) then xor1; lane q finalizes row q.
// ---------------------------------------------------------------------------
__global__ void __launch_bounds__(256, 2)
xin_kernel(const float* __restrict__ x,
           const float* __restrict__ W_in,
           const float* __restrict__ b_in)
{
    __shared__ float xs[2][4][XROW];

    const int tid = threadIdx.x;
    const int p   = tid >> 2;            // unit-pair 0..63
    const int q   = tid & 3;             // k-quarter
    const int j0  = 2 * p;
    const int k0  = 32 * q;

    // W_in rows j0, j0+1, cols [k0, k0+32): 64 floats in registers.
    ull wiA[16], wiB[16];
    {
        const ulonglong2* wpA = (const ulonglong2*)(W_in + (size_t)j0 * Dsz + k0);
        const ulonglong2* wpB = (const ulonglong2*)(W_in + (size_t)(j0 + 1) * Dsz + k0);
        #pragma unroll
        for (int c = 0; c < 8; ++c) {
            ulonglong2 vA = wpA[c];
            ulonglong2 vB = wpB[c];
            wiA[2 * c] = vA.x;  wiA[2 * c + 1] = vA.y;
            wiB[2 * c] = vB.x;  wiB[2 * c + 1] = vB.y;
        }
    }
    const float biA = b_in[j0];
    const float biB = b_in[j0 + 1];

    const int m0 = blockIdx.x * 128;

    // staging: 4 rows x 128 cols = 512 elems; thread owns e0=tid, e1=tid+256.
    const int e0r = tid >> 7,           e0c = tid & 127;
    const int e1r = (tid + 256) >> 7,   e1c = tid & 127;   // e1 col == e0 col
    float xf0 = x[(size_t)(m0 + e0r) * Dsz + e0c];
    float xf1 = x[(size_t)(m0 + e1r) * Dsz + e1c];

    #pragma unroll 1
    for (int ch = 0; ch < 32; ++ch) {
        float (*xb)[XROW] = xs[ch & 1];
        xb[e0r][e0c] = xf0;
        xb[e1r][e1c] = xf1;
        __syncthreads();

        if (ch < 31) {
            xf0 = x[(size_t)(m0 + (ch + 1) * 4 + e0r) * Dsz + e0c];
            xf1 = x[(size_t)(m0 + (ch + 1) * 4 + e1r) * Dsz + e1c];
        }

        // dot: 2 units x 4 rows over my k-quarter.
        ull aA[4], aB[4];
        #pragma unroll
        for (int r = 0; r < 4; ++r) { aA[r] = 0ull; aB[r] = 0ull; }
        const float* xr = &xb[0][k0];
        #pragma unroll
        for (int c = 0; c < 8; ++c) {
            #pragma unroll
            for (int r = 0; r < 4; ++r) {
                ulonglong2 v = *(const ulonglong2*)(xr + r * XROW + 4 * c);
                aA[r] = ffma2(wiA[2 * c],     v.x, aA[r]);
                aB[r] = ffma2(wiB[2 * c],     v.x, aB[r]);   // v.x reused
                aA[r] = ffma2(wiA[2 * c + 1], v.y, aA[r]);
                aB[r] = ffma2(wiB[2 * c + 1], v.y, aB[r]);   // v.y reused
            }
        }
        float pA[4], pB[4];
        #pragma unroll
        for (int r = 0; r < 4; ++r) { pA[r] = f2sum(aA[r]); pB[r] = f2sum(aB[r]); }

        // Round 1 (xor 2): keep rows {2*(q>>1), +1}; partner sends same rows.
        const int keepb = (q >> 1) * 2;
        const int sendb = ((q >> 1) ^ 1) * 2;
        float rA[2], rB[2];
        #pragma unroll
        for (int r = 0; r < 2; ++r) {
            rA[r] = pA[keepb + r] + __shfl_xor_sync(0xffffffffu, pA[sendb + r], 2);
            rB[r] = pB[keepb + r] + __shfl_xor_sync(0xffffffffu, pB[sendb + r], 2);
        }
        // Round 2 (xor 1): keep row index (q&1); final row = q.
        const int k1 = q & 1;
        const int s1 = k1 ^ 1;
        const float fA = rA[k1] + __shfl_xor_sync(0xffffffffu, rA[s1], 1);
        const float fB = rB[k1] + __shfl_xor_sync(0xffffffffu, rB[s1], 1);

        float2 o;
        o.x = fA + biA;
        o.y = fB + biB;
        *(float2*)&g_xin[(size_t)(m0 + ch * 4 + q) * Hsz + j0] = o;
    }
}

// ---------------------------------------------------------------------------
// Kernel 2: sequential scan — R13/R11 verbatim (measured 1400us).
// grid 256 x 128 threads, 2 rows/CTA, 2 CTAs/SM. Thread (p, hf): units
// j0=2p, 2p+1 over k-half [64hf,64hf+64); owns states (j0,row hf),(j0+1,row hf).
// 1 __syncthreads/unfold, shfl combine, MUFU.TANH, scalar mine/other offsets.
// ---------------------------------------------------------------------------
__global__ void __launch_bounds__(128, 2)
ltc_main(const float* __restrict__ W_r,
         const float* __restrict__ b_r,
         const float* __restrict__ W_fc,
         const float* __restrict__ b_fc,
         float* __restrict__ out)
{
    __shared__ float hs[2][2][HSTRIDE];   // [buf][row][padded k]
    __shared__ float red[2][64];

    const int tid  = threadIdx.x;
    const int p    = tid >> 1;
    const int hf   = tid & 1;
    const int j0   = 2 * p;
    const int base = blockIdx.x * 2;
    const int koff = hf * 68;                   // 64 floats + 4-float pad at k=64
    const int jph  = j0 + (j0 >= 64 ? 4 : 0);   // padded publish index
    const int rowM = hf * HSTRIDE;
    const int rowO = (hf ^ 1) * HSTRIDE;
    const int offM = rowM + koff;
    const int offO = rowO + koff;
    const int offP = rowM + jph;

    ull wA[32], wB[32];
    {
        const ulonglong2* wpA = (const ulonglong2*)(W_r + (size_t)j0 * Hsz + 64 * hf);
        const ulonglong2* wpB = (const ulonglong2*)(W_r + (size_t)(j0 + 1) * Hsz + 64 * hf);
        #pragma unroll
        for (int c = 0; c < 16; ++c) {
            ulonglong2 vA = wpA[c];
            ulonglong2 vB = wpB[c];
            wA[2 * c] = vA.x;  wA[2 * c + 1] = vA.y;
            wB[2 * c] = vB.x;  wB[2 * c + 1] = vB.y;
        }
    }

    const float2 bb2 = *(const float2*)&b_r[j0];

    float h0 = 0.f, h1 = 0.f;

    hs[0][0][offP]     = 0.f;
    hs[0][0][offP + 1] = 0.f;

    const size_t xi = (size_t)(base + hf) * Ssz * Hsz + j0;
    float2 xf = *(const float2*)&g_xin[xi];

    #pragma unroll 1
    for (int t = 0; t < Ssz; ++t) {
        const float xinA = xf.x + bb2.x;
        const float xinB = xf.y + bb2.y;
        if (t + 1 < Ssz)
            xf = *(const float2*)&g_xin[xi + (size_t)(t + 1) * Hsz];

        #pragma unroll 1
        for (int u = 0; u < UNFOLDS; ++u) {
            const float* hb = hs[u & 1][0];
            float*       hn = hs[(u + 1) & 1][0];
            __syncthreads();

            ull a0 = 0ull, a1 = 0ull, b0 = 0ull, b1 = 0ull;   // my row
            ull c0 = 0ull, c1 = 0ull, d0 = 0ull, d1 = 0ull;   // other row
            #pragma unroll
            for (int c = 0; c < 16; ++c) {
                ulonglong2 vM = *(const ulonglong2*)(hb + offM + 4 * c);
                ulonglong2 vO = *(const ulonglong2*)(hb + offO + 4 * c);
                a0 = ffma2(wA[2 * c],     vM.x, a0);
                b0 = ffma2(wB[2 * c],     vM.x, b0);
                a1 = ffma2(wA[2 * c + 1], vM.y, a1);
                b1 = ffma2(wB[2 * c + 1], vM.y, b1);
                c0 = ffma2(wA[2 * c],     vO.x, c0);
                d0 = ffma2(wB[2 * c],     vO.x, d0);
                c1 = ffma2(wA[2 * c + 1], vO.y, c1);
                d1 = ffma2(wB[2 * c + 1], vO.y, d1);
            }
            const float PaM = f2sum(a0) + f2sum(a1);
            const float PbM = f2sum(b0) + f2sum(b1);
            const float PaO = f2sum(c0) + f2sum(c1);
            const float PbO = f2sum(d0) + f2sum(d1);

            const float recvA = __shfl_xor_sync(0xffffffffu, PaO, 1);
            const float recvB = __shfl_xor_sync(0xffffffffu, PbO, 1);

            h0 = 0.9f * h0 + 0.1f * ftanh(PaM + recvA + xinA);
            h1 = 0.9f * h1 + 0.1f * ftanh(PbM + recvB + xinB);

            float2 st;  st.x = h0;  st.y = h1;
            *(float2*)(hn + offP) = st;
        }
    }

    __syncthreads();
    {
        const float2 wfc2 = *(const float2*)&W_fc[j0];
        red[hf][p] = h0 * wfc2.x + h1 * wfc2.y;
    }
    __syncthreads();

    const int wid = tid >> 5, lane = tid & 31;
    if (wid < 2) {
        float s = red[wid][lane] + red[wid][lane + 32];
        #pragma unroll
        for (int d = 16; d > 0; d >>= 1)
            s += __shfl_xor_sync(0xffffffffu, s, d);
        if (lane == 0)
            out[base + wid] = s + b_fc[0];
    }
}

extern "C" void kernel_launch(void* const* d_in, const int* in_sizes, int n_in,
                              void* d_out, int out_size)
{
    const float* x    = (const float*)d_in[0];
    const float* W_in = (const float*)d_in[1];
    const float* b_in = (const float*)d_in[2];
    const float* W_r  = (const float*)d_in[3];
    const float* b_r  = (const float*)d_in[4];
    const float* W_fc = (const float*)d_in[5];
    const float* b_fc = (const float*)d_in[6];
    float* out = (float*)d_out;

    xin_kernel<<<(Bsz * Ssz) / 128, 256>>>(x, W_in, b_in);
    ltc_main<<<Bsz / 2, 128>>>(W_r, b_r, W_fc, b_fc, out);
}

// round 17
// speedup vs baseline: 2.4893x; 1.4498x over previous
#include <cuda_runtime.h>
#include <cstdint>

// LTC scan, round 17 — consolidation at the measured optimum.
// R16 post-mortem: k-quarter xin split = 4-line LDS divergence + under-sized
// per-thread tiles -> 3.5x xin regression. Every xin restructure (R13 tail
// halving, R16 occupancy) has been neutral-or-worse => xin ~275us plateau.
// R17 = R13 two-kernel config verbatim, plus one safe micro-opt in the scan:
// add.rn.f32x2 pair-merge before f2sum (removes 4 FADDs + ~2 serial steps
// per unfold from the tanh dependency chain; proven harmless in R12).

#define Bsz 512
#define Ssz 512
#define Dsz 128
#define Hsz 128
#define UNFOLDS 6
#define HSTRIDE 136   // scan: 128 + 4 (pad at k=64) + 4 (row-stride bank shift)
#define XROW 132      // xin: padded row stride

typedef unsigned long long ull;

__device__ float g_xin[(size_t)Bsz * Ssz * Hsz];   // [b][s][h] scratch

__device__ __forceinline__ ull ffma2(ull a, ull b, ull c) {
    ull d;
    asm("fma.rn.f32x2 %0, %1, %2, %3;" : "=l"(d) : "l"(a), "l"(b), "l"(c));
    return d;
}

__device__ __forceinline__ ull addf2(ull a, ull b) {
    ull d;
    asm("add.rn.f32x2 %0, %1, %2;" : "=l"(d) : "l"(a), "l"(b));
    return d;
}

__device__ __forceinline__ float f2sum(ull v) {
    float lo, hi;
    asm("mov.b64 {%0, %1}, %2;" : "=f"(lo), "=f"(hi) : "l"(v));
    return lo + hi;
}

__device__ __forceinline__ float ftanh(float s) {
    float y;
    asm("tanh.approx.f32 %0, %1;" : "=f"(y) : "f"(s));   // MUFU.TANH
    return y;
}

// ---------------------------------------------------------------------------
// Kernel 1: xin[b,s,j] = sum_d x[b,s,d] * W_in[j,d] + b_in[j]
// R13 version (measured ~277us): 128 threads, thread (p = tid>>1, hf = tid&1):
// units j0=2p, 2p+1 over k-half [64hf, 64hf+64). 8 rows/chunk, 16 chunks.
// Cross-half combine via SHFL.XOR(1); lane finalizes rows [4hf, 4hf+4).
// ---------------------------------------------------------------------------
__global__ void __launch_bounds__(128, 2)
xin_kernel(const float* __restrict__ x,
           const float* __restrict__ W_in,
           const float* __restrict__ b_in)
{
    __shared__ float xs[2][8][XROW];

    const int tid = threadIdx.x;
    const int p   = tid >> 1;
    const int hf  = tid & 1;
    const int j0  = 2 * p;

    // W_in rows j0, j0+1, cols [64hf, 64hf+64): 128 floats in registers.
    ull wiA[32], wiB[32];
    {
        const ulonglong2* wpA = (const ulonglong2*)(W_in + (size_t)j0 * Dsz + 64 * hf);
        const ulonglong2* wpB = (const ulonglong2*)(W_in + (size_t)(j0 + 1) * Dsz + 64 * hf);
        #pragma unroll
        for (int c = 0; c < 16; ++c) {
            ulonglong2 vA = wpA[c];
            ulonglong2 vB = wpB[c];
            wiA[2 * c] = vA.x;  wiA[2 * c + 1] = vA.y;
            wiB[2 * c] = vB.x;  wiB[2 * c + 1] = vB.y;
        }
    }
    const float biA = b_in[j0];
    const float biB = b_in[j0 + 1];

    const int m0 = blockIdx.x * 128;

    float xf[8];
    #pragma unroll
    for (int r = 0; r < 8; ++r)
        xf[r] = x[(size_t)(m0 + r) * Dsz + tid];

    #pragma unroll 1
    for (int ch = 0; ch < 16; ++ch) {
        float (*xb)[XROW] = xs[ch & 1];
        #pragma unroll
        for (int r = 0; r < 8; ++r)
            xb[r][tid] = xf[r];
        __syncthreads();

        if (ch < 15) {
            #pragma unroll
            for (int r = 0; r < 8; ++r)
                xf[r] = x[(size_t)(m0 + (ch + 1) * 8 + r) * Dsz + tid];
        }

        // dot: 2 units x 8 rows over my k-half (each 16B x-load feeds 4 FFMA2)
        ull aA[8], aB[8];
        #pragma unroll
        for (int r = 0; r < 8; ++r) { aA[r] = 0ull; aB[r] = 0ull; }
        const float* xr = &xb[0][64 * hf];
        #pragma unroll
        for (int c = 0; c < 16; ++c) {
            #pragma unroll
            for (int r = 0; r < 8; ++r) {
                ulonglong2 v = *(const ulonglong2*)(xr + r * XROW + 4 * c);
                aA[r] = ffma2(wiA[2 * c],     v.x, aA[r]);
                aB[r] = ffma2(wiB[2 * c],     v.x, aB[r]);   // v.x reused
                aA[r] = ffma2(wiA[2 * c + 1], v.y, aA[r]);
                aB[r] = ffma2(wiB[2 * c + 1], v.y, aB[r]);   // v.y reused
            }
        }

        float pA[8], pB[8];
        #pragma unroll
        for (int r = 0; r < 8; ++r) { pA[r] = f2sum(aA[r]); pB[r] = f2sum(aB[r]); }

        // Lane finalizes rows [4hf, 4hf+4); sends the other 4 rows' partials.
        #pragma unroll
        for (int rr = 0; rr < 4; ++rr) {
            const int rk = 4 * hf + rr;          // row I keep
            const int rs = 4 * (hf ^ 1) + rr;    // row I send
            const float recvA = __shfl_xor_sync(0xffffffffu, pA[rs], 1);
            const float recvB = __shfl_xor_sync(0xffffffffu, pB[rs], 1);
            float2 o;
            o.x = pA[rk] + recvA + biA;
            o.y = pB[rk] + recvB + biB;
            *(float2*)&g_xin[(size_t)(m0 + ch * 8 + rk) * Hsz + j0] = o;
        }
    }
}

// ---------------------------------------------------------------------------
// Kernel 2: sequential scan — R13/R11 structure (measured 1400us) + addf2
// tail merge. grid 256 x 128 threads, 2 rows/CTA, 2 CTAs/SM.
// Thread (p, hf): units j0=2p, 2p+1 over k-half [64hf,64hf+64); owns states
// (j0,row hf),(j0+1,row hf). 1 __syncthreads/unfold, shfl combine, MUFU.TANH.
// ---------------------------------------------------------------------------
__global__ void __launch_bounds__(128, 2)
ltc_main(const float* __restrict__ W_r,
         const float* __restrict__ b_r,
         const float* __restrict__ W_fc,
         const float* __restrict__ b_fc,
         float* __restrict__ out)
{
    __shared__ float hs[2][2][HSTRIDE];   // [buf][row][padded k]
    __shared__ float red[2][64];

    const int tid  = threadIdx.x;
    const int p    = tid >> 1;
    const int hf   = tid & 1;
    const int j0   = 2 * p;
    const int base = blockIdx.x * 2;
    const int koff = hf * 68;                   // 64 floats + 4-float pad at k=64
    const int jph  = j0 + (j0 >= 64 ? 4 : 0);   // padded publish index
    const int rowM = hf * HSTRIDE;
    const int rowO = (hf ^ 1) * HSTRIDE;
    const int offM = rowM + koff;
    const int offO = rowO + koff;
    const int offP = rowM + jph;

    ull wA[32], wB[32];
    {
        const ulonglong2* wpA = (const ulonglong2*)(W_r + (size_t)j0 * Hsz + 64 * hf);
        const ulonglong2* wpB = (const ulonglong2*)(W_r + (size_t)(j0 + 1) * Hsz + 64 * hf);
        #pragma unroll
        for (int c = 0; c < 16; ++c) {
            ulonglong2 vA = wpA[c];
            ulonglong2 vB = wpB[c];
            wA[2 * c] = vA.x;  wA[2 * c + 1] = vA.y;
            wB[2 * c] = vB.x;  wB[2 * c + 1] = vB.y;
        }
    }

    const float2 bb2 = *(const float2*)&b_r[j0];

    float h0 = 0.f, h1 = 0.f;

    hs[0][0][offP]     = 0.f;
    hs[0][0][offP + 1] = 0.f;

    const size_t xi = (size_t)(base + hf) * Ssz * Hsz + j0;
    float2 xf = *(const float2*)&g_xin[xi];

    #pragma unroll 1
    for (int t = 0; t < Ssz; ++t) {
        const float xinA = xf.x + bb2.x;
        const float xinB = xf.y + bb2.y;
        if (t + 1 < Ssz)
            xf = *(const float2*)&g_xin[xi + (size_t)(t + 1) * Hsz];

        #pragma unroll 1
        for (int u = 0; u < UNFOLDS; ++u) {
            const float* hb = hs[u & 1][0];
            float*       hn = hs[(u + 1) & 1][0];
            __syncthreads();

            ull a0 = 0ull, a1 = 0ull, b0 = 0ull, b1 = 0ull;   // my row
            ull c0 = 0ull, c1 = 0ull, d0 = 0ull, d1 = 0ull;   // other row
            #pragma unroll
            for (int c = 0; c < 16; ++c) {
                ulonglong2 vM = *(const ulonglong2*)(hb + offM + 4 * c);
                ulonglong2 vO = *(const ulonglong2*)(hb + offO + 4 * c);
                a0 = ffma2(wA[2 * c],     vM.x, a0);
                b0 = ffma2(wB[2 * c],     vM.x, b0);
                a1 = ffma2(wA[2 * c + 1], vM.y, a1);
                b1 = ffma2(wB[2 * c + 1], vM.y, b1);
                c0 = ffma2(wA[2 * c],     vO.x, c0);
                d0 = ffma2(wB[2 * c],     vO.x, d0);
                c1 = ffma2(wA[2 * c + 1], vO.y, c1);
                d1 = ffma2(wB[2 * c + 1], vO.y, d1);
            }
            // addf2 pair-merge: one packed add replaces two scalar FADD paths,
            // shortening the serial chain into tanh.
            const float PaM = f2sum(addf2(a0, a1));
            const float PbM = f2sum(addf2(b0, b1));
            const float PaO = f2sum(addf2(c0, c1));
            const float PbO = f2sum(addf2(d0, d1));

            const float recvA = __shfl_xor_sync(0xffffffffu, PaO, 1);
            const float recvB = __shfl_xor_sync(0xffffffffu, PbO, 1);

            h0 = 0.9f * h0 + 0.1f * ftanh(PaM + recvA + xinA);
            h1 = 0.9f * h1 + 0.1f * ftanh(PbM + recvB + xinB);

            float2 st;  st.x = h0;  st.y = h1;
            *(float2*)(hn + offP) = st;
        }
    }

    __syncthreads();
    {
        const float2 wfc2 = *(const float2*)&W_fc[j0];
        red[hf][p] = h0 * wfc2.x + h1 * wfc2.y;
    }
    __syncthreads();

    const int wid = tid >> 5, lane = tid & 31;
    if (wid < 2) {
        float s = red[wid][lane] + red[wid][lane + 32];
        #pragma unroll
        for (int d = 16; d > 0; d >>= 1)
            s += __shfl_xor_sync(0xffffffffu, s, d);
        if (lane == 0)
            out[base + wid] = s + b_fc[0];
    }
}

extern "C" void kernel_launch(void* const* d_in, const int* in_sizes, int n_in,
                              void* d_out, int out_size)
{
    const float* x    = (const float*)d_in[0];
    const float* W_in = (const float*)d_in[1];
    const float* b_in = (const float*)d_in[2];
    const float* W_r  = (const float*)d_in[3];
    const float* b_r  = (const float*)d_in[4];
    const float* W_fc = (const float*)d_in[5];
    const float* b_fc = (const float*)d_in[6];
    float* out = (float*)d_out;

    xin_kernel<<<(Bsz * Ssz) / 128, 128>>>(x, W_in, b_in);
    ltc_main<<<Bsz / 2, 128>>>(W_r, b_r, W_fc, b_fc, out);
}